// round 7
// baseline (speedup 1.0000x reference)
#include <cuda_runtime.h>
#include <math.h>
#include <stdint.h>

#define NB 64
#define NS 4096
#define ND 256
#define SPLIT 8
#define CHUNK (NS / SPLIT)        // 512 rows per CTA
#define BLOCK 256
#define NWARP 8
#define RPW (CHUNK / NWARP)       // 64 rows per warp
#define DEPTH 6                   // cp.async ring depth (rows in flight per warp)

// smem partition (dynamic): ring buffers, then combine scratch
#define SM_BUF   0
#define SM_ACC   (NWARP * DEPTH * 1024)            // 49152
#define SM_DEN   (SM_ACC + NWARP * ND * 4)         // 57344
#define SM_RED   (SM_DEN + NWARP * 4)              // 57376
#define SM_FLAG  (SM_RED + NWARP * 4)              // 57408
#define SM_TOTAL (SM_FLAG + 16)                    // 57424

__device__ float g_num[NB * SPLIT * ND];
__device__ float g_den[NB * SPLIT];
__device__ unsigned int g_cnt[NB];                 // zero-init; winner resets

__device__ __forceinline__ void cp16(uint32_t dst, const float* src) {
    asm volatile("cp.async.cg.shared.global [%0], [%1], 16;"
                 :: "r"(dst), "l"(src) : "memory");
}
__device__ __forceinline__ void cp_commit() {
    asm volatile("cp.async.commit_group;" ::: "memory");
}
template<int N> __device__ __forceinline__ void cp_wait() {
    asm volatile("cp.async.wait_group %0;" :: "n"(N) : "memory");
}

__device__ __forceinline__ float tanh_fast(float x) {
    float e = __expf(2.0f * x);
    return 1.0f - __fdividef(2.0f, e + 1.0f);
}

__global__ __launch_bounds__(BLOCK)
void att_fused(const float* __restrict__ aspect,
               const float* __restrict__ memory,
               const float* __restrict__ W,
               const float* __restrict__ bias,
               float* __restrict__ out)
{
    extern __shared__ char smem[];
    float* s_acc  = (float*)(smem + SM_ACC);       // [NWARP][ND]
    float* s_den  = (float*)(smem + SM_DEN);
    float* s_red  = (float*)(smem + SM_RED);
    int*   s_flag = (int*)  (smem + SM_FLAG);

    const int b     = blockIdx.y;
    const int chunk = blockIdx.x;
    const int tid   = threadIdx.x;
    const int warp  = tid >> 5;
    const int lane  = tid & 31;

    // This warp's rows and its private smem ring
    const float* memb = memory
        + ((size_t)b * NS + (size_t)chunk * CHUNK + (size_t)warp * RPW) * ND;
    const uint32_t ring = (uint32_t)__cvta_generic_to_shared(smem + SM_BUF)
                        + warp * (DEPTH * 1024);

    // Prologue: fill the ring (DEPTH rows, one commit group per row).
    #pragma unroll
    for (int r = 0; r < DEPTH; r++) {
        const float*  p = memb + (size_t)r * ND + lane * 8;
        const uint32_t d = ring + r * 1024 + lane * 16;
        cp16(d, p);
        cp16(d + 512, p + 4);
        cp_commit();
    }

    // a_b = aspect[b].Wa + bias (overlapped with prologue loads landing)
    float av = aspect[b * ND + tid] * W[ND + tid];
    #pragma unroll
    for (int o = 16; o; o >>= 1) av += __shfl_xor_sync(0xFFFFFFFFu, av, o);
    if (lane == 0) s_red[warp] = av;
    __syncthreads();
    float a_b = bias[0];
    #pragma unroll
    for (int w = 0; w < NWARP; w++) a_b += s_red[w];

    // Wm slice for this lane's 8 dims
    const float4 w0 = *(const float4*)(W + lane * 8);
    const float4 w1 = *(const float4*)(W + lane * 8 + 4);

    float acc0 = 0.f, acc1 = 0.f, acc2 = 0.f, acc3 = 0.f;
    float acc4 = 0.f, acc5 = 0.f, acc6 = 0.f, acc7 = 0.f;
    float den = 0.f;
    int slot = 0;

    // Steady state: wait oldest, consume, refill same slot (after last use).
    for (int r = 0; r < RPW - DEPTH; r++) {
        cp_wait<DEPTH - 1>();

        const uint32_t sbase = ring + slot * 1024 + lane * 16;
        float4 va, vb;
        asm volatile("ld.shared.v4.f32 {%0,%1,%2,%3}, [%4];"
                     : "=f"(va.x), "=f"(va.y), "=f"(va.z), "=f"(va.w) : "r"(sbase));
        asm volatile("ld.shared.v4.f32 {%0,%1,%2,%3}, [%4];"
                     : "=f"(vb.x), "=f"(vb.y), "=f"(vb.z), "=f"(vb.w) : "r"(sbase + 512));

        float s = va.x * w0.x;
        s = fmaf(va.y, w0.y, s); s = fmaf(va.z, w0.z, s); s = fmaf(va.w, w0.w, s);
        s = fmaf(vb.x, w1.x, s); s = fmaf(vb.y, w1.y, s);
        s = fmaf(vb.z, w1.z, s); s = fmaf(vb.w, w1.w, s);
        #pragma unroll
        for (int o = 16; o; o >>= 1) s += __shfl_xor_sync(0xFFFFFFFFu, s, o);

        const float gi = tanh_fast(s + a_b);
        const float w  = __expf(gi - 1.0f);     // gi in [-1,1]: fixed max = 1
        den += w;
        acc0 = fmaf(w, va.x, acc0); acc1 = fmaf(w, va.y, acc1);
        acc2 = fmaf(w, va.z, acc2); acc3 = fmaf(w, va.w, acc3);
        acc4 = fmaf(w, vb.x, acc4); acc5 = fmaf(w, vb.y, acc5);
        acc6 = fmaf(w, vb.z, acc6); acc7 = fmaf(w, vb.w, acc7);

        // Refill this slot with row r+DEPTH (issued after all reads of the slot)
        const float*  p = memb + (size_t)(r + DEPTH) * ND + lane * 8;
        const uint32_t d = ring + slot * 1024 + lane * 16;
        cp16(d, p);
        cp16(d + 512, p + 4);
        cp_commit();

        if (++slot == DEPTH) slot = 0;
    }

    // Tail: drain remaining DEPTH rows.
    cp_wait<0>();
    #pragma unroll
    for (int r = RPW - DEPTH; r < RPW; r++) {
        const uint32_t sbase = ring + slot * 1024 + lane * 16;
        float4 va, vb;
        asm volatile("ld.shared.v4.f32 {%0,%1,%2,%3}, [%4];"
                     : "=f"(va.x), "=f"(va.y), "=f"(va.z), "=f"(va.w) : "r"(sbase));
        asm volatile("ld.shared.v4.f32 {%0,%1,%2,%3}, [%4];"
                     : "=f"(vb.x), "=f"(vb.y), "=f"(vb.z), "=f"(vb.w) : "r"(sbase + 512));

        float s = va.x * w0.x;
        s = fmaf(va.y, w0.y, s); s = fmaf(va.z, w0.z, s); s = fmaf(va.w, w0.w, s);
        s = fmaf(vb.x, w1.x, s); s = fmaf(vb.y, w1.y, s);
        s = fmaf(vb.z, w1.z, s); s = fmaf(vb.w, w1.w, s);
        #pragma unroll
        for (int o = 16; o; o >>= 1) s += __shfl_xor_sync(0xFFFFFFFFu, s, o);

        const float gi = tanh_fast(s + a_b);
        const float w  = __expf(gi - 1.0f);
        den += w;
        acc0 = fmaf(w, va.x, acc0); acc1 = fmaf(w, va.y, acc1);
        acc2 = fmaf(w, va.z, acc2); acc3 = fmaf(w, va.w, acc3);
        acc4 = fmaf(w, vb.x, acc4); acc5 = fmaf(w, vb.y, acc5);
        acc6 = fmaf(w, vb.z, acc6); acc7 = fmaf(w, vb.w, acc7);

        if (++slot == DEPTH) slot = 0;
    }

    // Combine 8 warps -> per-CTA partial in gmem
    float4* sa = (float4*)&s_acc[warp * ND + lane * 8];
    sa[0] = make_float4(acc0, acc1, acc2, acc3);
    sa[1] = make_float4(acc4, acc5, acc6, acc7);
    if (lane == 0) s_den[warp] = den;
    __syncthreads();

    const int idx = b * SPLIT + chunk;
    {
        float v = 0.f;
        #pragma unroll
        for (int w = 0; w < NWARP; w++) v += s_acc[w * ND + tid];
        g_num[(size_t)idx * ND + tid] = v;
    }
    if (tid == 0) {
        float v = 0.f;
        #pragma unroll
        for (int w = 0; w < NWARP; w++) v += s_den[w];
        g_den[idx] = v;
    }

    // Completion counter: last CTA of this batch reduces the SPLIT partials.
    __threadfence();
    __syncthreads();
    if (tid == 0) {
        unsigned old = atomicAdd(&g_cnt[b], 1u);
        s_flag[0] = (old == SPLIT - 1) ? 1 : 0;
    }
    __syncthreads();
    if (s_flag[0]) {
        __threadfence();                 // acquire: see other CTAs' partials
        if (tid == 0) g_cnt[b] = 0;      // reset for next graph replay
        float num = 0.f, dsum = 0.f;
        #pragma unroll
        for (int i = 0; i < SPLIT; i++) {
            num  += g_num[(size_t)(b * SPLIT + i) * ND + tid];
            dsum += g_den[b * SPLIT + i];
        }
        out[b * ND + tid] = __fdividef(num, dsum);
    }
}

extern "C" void kernel_launch(void* const* d_in, const int* in_sizes, int n_in,
                              void* d_out, int out_size)
{
    const float* aspect = (const float*)d_in[0];  // (64, 1, 256)
    const float* memory = (const float*)d_in[1];  // (64, 4096, 256)
    const float* W      = (const float*)d_in[2];  // (512, 1)
    const float* bias   = (const float*)d_in[3];  // (1,)
    float* out = (float*)d_out;                   // (64, 256)

    static bool attr_set = false;
    if (!attr_set) {
        cudaFuncSetAttribute(att_fused,
                             cudaFuncAttributeMaxDynamicSharedMemorySize, SM_TOTAL);
        attr_set = true;
    }

    dim3 grid(SPLIT, NB);                          // 512 CTAs = 1 wave @ 4/SM
    att_fused<<<grid, BLOCK, SM_TOTAL>>>(aspect, memory, W, bias, out);
}

// round 8
// speedup vs baseline: 1.6410x; 1.6410x over previous
#include <cuda_runtime.h>
#include <math.h>
#include <stdint.h>

#define NB 64
#define NS 4096
#define ND 256
#define SPLIT 32
#define CHUNK (NS / SPLIT)        // 128 rows per CTA
#define BLOCK 128
#define NWARP 4
#define RPW (CHUNK / NWARP)       // 32 rows per warp
#define RUN 4                     // rows per register batch

__device__ float g_num[NB * SPLIT * ND];
__device__ float g_den[NB * SPLIT];
__device__ unsigned int g_cnt[NB];   // zero-init; winning CTA resets

struct Rows { float4 a[RUN]; float4 b[RUN]; };

__device__ __forceinline__ float tanh_fast(float x) {
    float e = __expf(2.0f * x);
    return 1.0f - __fdividef(2.0f, e + 1.0f);
}

__device__ __forceinline__ void load_rows(Rows& R, const float* __restrict__ base,
                                          int r0, int lane) {
    #pragma unroll
    for (int r = 0; r < RUN; r++) {
        const float* p = base + (size_t)(r0 + r) * ND + lane * 8;
        R.a[r] = *(const float4*)(p);
        R.b[r] = *(const float4*)(p + 4);
    }
}

__device__ __forceinline__ void process_rows(const Rows& R,
                                             const float4 w0, const float4 w1,
                                             const float a_b,
                                             float* acc, float& den) {
    float d[RUN];
    #pragma unroll
    for (int r = 0; r < RUN; r++) {
        float s = R.a[r].x * w0.x;
        s = fmaf(R.a[r].y, w0.y, s); s = fmaf(R.a[r].z, w0.z, s);
        s = fmaf(R.a[r].w, w0.w, s);
        s = fmaf(R.b[r].x, w1.x, s); s = fmaf(R.b[r].y, w1.y, s);
        s = fmaf(R.b[r].z, w1.z, s); s = fmaf(R.b[r].w, w1.w, s);
        d[r] = s;
    }
    // 4 interleaved butterfly reductions
    #pragma unroll
    for (int o = 16; o; o >>= 1) {
        #pragma unroll
        for (int r = 0; r < RUN; r++)
            d[r] += __shfl_xor_sync(0xFFFFFFFFu, d[r], o);
    }
    #pragma unroll
    for (int r = 0; r < RUN; r++) {
        const float gi = tanh_fast(d[r] + a_b);
        const float w  = __expf(gi - 1.0f);     // gi in [-1,1]: fixed max = 1
        den += w;
        acc[0] = fmaf(w, R.a[r].x, acc[0]); acc[1] = fmaf(w, R.a[r].y, acc[1]);
        acc[2] = fmaf(w, R.a[r].z, acc[2]); acc[3] = fmaf(w, R.a[r].w, acc[3]);
        acc[4] = fmaf(w, R.b[r].x, acc[4]); acc[5] = fmaf(w, R.b[r].y, acc[5]);
        acc[6] = fmaf(w, R.b[r].z, acc[6]); acc[7] = fmaf(w, R.b[r].w, acc[7]);
    }
}

__global__ __launch_bounds__(BLOCK)
void att_fused(const float* __restrict__ aspect,
               const float* __restrict__ memory,
               const float* __restrict__ W,
               const float* __restrict__ bias,
               float* __restrict__ out)
{
    __shared__ float s_red[NWARP];
    __shared__ float s_acc[NWARP][ND];
    __shared__ float s_den[NWARP];
    __shared__ int   s_flag;

    const int b     = blockIdx.y;
    const int chunk = blockIdx.x;
    const int tid   = threadIdx.x;
    const int warp  = tid >> 5;
    const int lane  = tid & 31;

    const float* memb = memory
        + ((size_t)b * NS + (size_t)chunk * CHUNK + (size_t)warp * RPW) * ND;

    // Prologue: batch A = rows 0..RUN-1 (in flight during aspect reduction)
    Rows A, Bf;
    load_rows(A, memb, 0, lane);

    // a_b = aspect[b].Wa + bias
    float av = aspect[b * ND + tid]       * W[ND + tid]
             + aspect[b * ND + tid + 128] * W[ND + tid + 128];
    #pragma unroll
    for (int o = 16; o; o >>= 1) av += __shfl_xor_sync(0xFFFFFFFFu, av, o);
    if (lane == 0) s_red[warp] = av;
    __syncthreads();
    const float a_b = bias[0] + s_red[0] + s_red[1] + s_red[2] + s_red[3];

    const float4 w0 = *(const float4*)(W + lane * 8);
    const float4 w1 = *(const float4*)(W + lane * 8 + 4);

    float acc[8] = {0.f, 0.f, 0.f, 0.f, 0.f, 0.f, 0.f, 0.f};
    float den = 0.f;

    // Software-pipelined: prefetch next batch BEFORE consuming current one.
    #pragma unroll 1
    for (int r0 = 0; r0 < RPW; r0 += 2 * RUN) {
        load_rows(Bf, memb, r0 + RUN, lane);          // overlap with A's chain
        process_rows(A, w0, w1, a_b, acc, den);
        if (r0 + 2 * RUN < RPW)
            load_rows(A, memb, r0 + 2 * RUN, lane);   // overlap with B's chain
        process_rows(Bf, w0, w1, a_b, acc, den);
    }

    // Combine warps -> per-CTA partial
    float4* sa = (float4*)&s_acc[warp][lane * 8];
    sa[0] = make_float4(acc[0], acc[1], acc[2], acc[3]);
    sa[1] = make_float4(acc[4], acc[5], acc[6], acc[7]);
    if (lane == 0) s_den[warp] = den;
    __syncthreads();

    const int idx = b * SPLIT + chunk;
    #pragma unroll
    for (int k = 0; k < 2; k++) {
        const int d = tid + k * BLOCK;
        g_num[(size_t)idx * ND + d] =
            s_acc[0][d] + s_acc[1][d] + s_acc[2][d] + s_acc[3][d];
    }
    if (tid == 0)
        g_den[idx] = s_den[0] + s_den[1] + s_den[2] + s_den[3];

    // Last CTA of this batch reduces the SPLIT partials (fused finisher).
    __threadfence();
    __syncthreads();
    if (tid == 0) {
        unsigned old = atomicAdd(&g_cnt[b], 1u);
        s_flag = (old == SPLIT - 1) ? 1 : 0;
    }
    __syncthreads();
    if (s_flag) {
        __threadfence();                  // acquire: other CTAs' partials visible
        if (tid == 0) g_cnt[b] = 0;       // reset for next graph replay
        float num0 = 0.f, num1 = 0.f, dsum = 0.f;
        #pragma unroll 4
        for (int i = 0; i < SPLIT; i++) {
            const size_t base = (size_t)(b * SPLIT + i) * ND;
            num0 += g_num[base + tid];
            num1 += g_num[base + tid + 128];
            dsum += g_den[b * SPLIT + i];
        }
        const float inv = __fdividef(1.0f, dsum);
        out[b * ND + tid]       = num0 * inv;
        out[b * ND + tid + 128] = num1 * inv;
    }
}

extern "C" void kernel_launch(void* const* d_in, const int* in_sizes, int n_in,
                              void* d_out, int out_size)
{
    const float* aspect = (const float*)d_in[0];  // (64, 1, 256)
    const float* memory = (const float*)d_in[1];  // (64, 4096, 256)
    const float* W      = (const float*)d_in[2];  // (512, 1)
    const float* bias   = (const float*)d_in[3];  // (1,)
    float* out = (float*)d_out;                   // (64, 256)

    dim3 grid(SPLIT, NB);                          // 2048 CTAs
    att_fused<<<grid, BLOCK>>>(aspect, memory, W, bias, out);
}

// round 9
// speedup vs baseline: 1.8875x; 1.1502x over previous
#include <cuda_runtime.h>
#include <math.h>
#include <stdint.h>

#define NB 64
#define NS 4096
#define ND 256
#define SPLIT 16
#define CHUNK (NS / SPLIT)            // 256 rows per CTA
#define BLOCK 128
#define NWARP 4
#define TILE_ROWS 16
#define NTILES (CHUNK / TILE_ROWS)    // 16 tiles per CTA
#define TILE_BYTES (TILE_ROWS * ND * 4)   // 16384
#define DEPTH 3                       // smem ring depth (tiles in flight)
#define RPWT (TILE_ROWS / NWARP)      // 4 rows per warp per tile

// smem layout (dynamic)
#define SM_BUF   0
#define SM_MBAR  (DEPTH * TILE_BYTES)                 // 49152
#define SM_ACC   (SM_MBAR + DEPTH * 8)                // 49176 -> align
#define SM_ACC_A ((SM_ACC + 15) & ~15)
#define SM_DEN   (SM_ACC_A + NWARP * ND * 4)
#define SM_RED   (SM_DEN + NWARP * 4)
#define SM_FLAG  (SM_RED + NWARP * 4)
#define SM_TOTAL (SM_FLAG + 16)

__device__ float g_num[NB * SPLIT * ND];
__device__ float g_den[NB * SPLIT];
__device__ unsigned int g_cnt[NB];    // zero-init; winning CTA resets

__device__ __forceinline__ float tanh_fast(float x) {
    float e = __expf(2.0f * x);
    return 1.0f - __fdividef(2.0f, e + 1.0f);
}

__device__ __forceinline__ void mbar_init(uint32_t mbar, uint32_t count) {
    asm volatile("mbarrier.init.shared.b64 [%0], %1;" :: "r"(mbar), "r"(count) : "memory");
}
__device__ __forceinline__ void mbar_expect_tx(uint32_t mbar, uint32_t bytes) {
    asm volatile("mbarrier.arrive.expect_tx.shared.b64 _, [%0], %1;"
                 :: "r"(mbar), "r"(bytes) : "memory");
}
__device__ __forceinline__ void bulk_cp(uint32_t dst, const void* src, uint32_t mbar) {
    asm volatile("cp.async.bulk.shared::cta.global.mbarrier::complete_tx::bytes "
                 "[%0], [%1], %2, [%3];"
                 :: "r"(dst), "l"(src), "r"((uint32_t)TILE_BYTES), "r"(mbar) : "memory");
}
__device__ __forceinline__ void mbar_wait(uint32_t mbar, uint32_t parity) {
    uint32_t done;
    asm volatile("{\n\t.reg .pred p;\n\t"
                 "mbarrier.try_wait.parity.acquire.cta.shared::cta.b64 p, [%1], %2;\n\t"
                 "selp.b32 %0, 1, 0, p;\n\t}"
                 : "=r"(done) : "r"(mbar), "r"(parity) : "memory");
    if (!done) {
        asm volatile("{\n\t.reg .pred P1;\n\t"
                     "W_%=:\n\t"
                     "mbarrier.try_wait.parity.acquire.cta.shared::cta.b64 P1, [%0], %1, 0x989680;\n\t"
                     "@P1 bra.uni D_%=;\n\t"
                     "bra.uni W_%=;\n\t"
                     "D_%=:\n\t}"
                     :: "r"(mbar), "r"(parity) : "memory");
    }
}

__global__ __launch_bounds__(BLOCK)
void att_fused(const float* __restrict__ aspect,
               const float* __restrict__ memory,
               const float* __restrict__ W,
               const float* __restrict__ bias,
               float* __restrict__ out)
{
    extern __shared__ char smem[];
    float* sbuf   = (float*)(smem + SM_BUF);
    float* s_acc  = (float*)(smem + SM_ACC_A);     // [NWARP][ND]
    float* s_den  = (float*)(smem + SM_DEN);
    float* s_red  = (float*)(smem + SM_RED);
    int*   s_flag = (int*)  (smem + SM_FLAG);
    const uint32_t smem_u32 = (uint32_t)__cvta_generic_to_shared(smem);
    const uint32_t mbar0    = smem_u32 + SM_MBAR;

    const int b     = blockIdx.y;
    const int chunk = blockIdx.x;
    const int tid   = threadIdx.x;
    const int warp  = tid >> 5;
    const int lane  = tid & 31;

    const float* memb = memory + ((size_t)b * NS + (size_t)chunk * CHUNK) * ND;

    // Init ring barriers and prime DEPTH tiles.
    if (tid == 0) {
        #pragma unroll
        for (int s = 0; s < DEPTH; s++) mbar_init(mbar0 + s * 8, 1);
        // make inits visible to the async proxy before bulk copies target them
        asm volatile("fence.proxy.async.shared::cta;" ::: "memory");
        #pragma unroll
        for (int s = 0; s < DEPTH; s++) {
            mbar_expect_tx(mbar0 + s * 8, TILE_BYTES);
            bulk_cp(smem_u32 + SM_BUF + s * TILE_BYTES,
                    memb + (size_t)s * TILE_ROWS * ND, mbar0 + s * 8);
        }
    }

    // a_b = aspect[b].Wa + bias  (overlaps with primed loads)
    float av = aspect[b * ND + tid]       * W[ND + tid]
             + aspect[b * ND + tid + 128] * W[ND + tid + 128];
    #pragma unroll
    for (int o = 16; o; o >>= 1) av += __shfl_xor_sync(0xFFFFFFFFu, av, o);
    if (lane == 0) s_red[warp] = av;
    __syncthreads();   // also orders mbar_init with all threads' first wait
    const float a_b = bias[0] + s_red[0] + s_red[1] + s_red[2] + s_red[3];

    // Lane owns dims {lane + 32k}, k=0..7  (conflict-free stride-32 LDS)
    float w[8];
    #pragma unroll
    for (int k = 0; k < 8; k++) w[k] = W[lane + 32 * k];

    float acc[8] = {0.f, 0.f, 0.f, 0.f, 0.f, 0.f, 0.f, 0.f};
    float den = 0.f;

    #pragma unroll 1
    for (int t = 0; t < NTILES; t++) {
        const int slot = t % DEPTH;
        const uint32_t parity = (t / DEPTH) & 1;
        mbar_wait(mbar0 + slot * 8, parity);

        // Consume: warp takes rows [4*warp, 4*warp+4) of this 16-row tile.
        const float* srow = sbuf + slot * (TILE_ROWS * ND) + (warp * RPWT) * ND + lane;

        float m[RPWT][8];
        #pragma unroll
        for (int r = 0; r < RPWT; r++)
            #pragma unroll
            for (int k = 0; k < 8; k++)
                m[r][k] = srow[r * ND + 32 * k];

        float d[RPWT];
        #pragma unroll
        for (int r = 0; r < RPWT; r++) {
            float s = m[r][0] * w[0];
            #pragma unroll
            for (int k = 1; k < 8; k++) s = fmaf(m[r][k], w[k], s);
            d[r] = s;
        }
        #pragma unroll
        for (int o = 16; o; o >>= 1) {
            #pragma unroll
            for (int r = 0; r < RPWT; r++)
                d[r] += __shfl_xor_sync(0xFFFFFFFFu, d[r], o);
        }
        #pragma unroll
        for (int r = 0; r < RPWT; r++) {
            const float gi = tanh_fast(d[r] + a_b);
            const float g  = __expf(gi - 1.0f);     // gi in [-1,1]: fixed max = 1
            den += g;
            #pragma unroll
            for (int k = 0; k < 8; k++) acc[k] = fmaf(g, m[r][k], acc[k]);
        }

        __syncthreads();   // all warps done with this slot
        if (tid == 0 && t + DEPTH < NTILES) {
            mbar_expect_tx(mbar0 + slot * 8, TILE_BYTES);
            bulk_cp(smem_u32 + SM_BUF + slot * TILE_BYTES,
                    memb + (size_t)(t + DEPTH) * TILE_ROWS * ND, mbar0 + slot * 8);
        }
    }

    // Combine warps -> per-CTA partial. s_acc layout: dim d = lane + 32k.
    #pragma unroll
    for (int k = 0; k < 8; k++) s_acc[warp * ND + lane + 32 * k] = acc[k];
    if (lane == 0) s_den[warp] = den;
    __syncthreads();

    const int idx = b * SPLIT + chunk;
    #pragma unroll
    for (int k = 0; k < 2; k++) {
        const int d = tid + k * BLOCK;
        g_num[(size_t)idx * ND + d] =
            s_acc[0 * ND + d] + s_acc[1 * ND + d] + s_acc[2 * ND + d] + s_acc[3 * ND + d];
    }
    if (tid == 0)
        g_den[idx] = s_den[0] + s_den[1] + s_den[2] + s_den[3];

    // Fused finisher: last CTA of this batch reduces the SPLIT partials.
    __threadfence();
    __syncthreads();
    if (tid == 0) {
        unsigned old = atomicAdd(&g_cnt[b], 1u);
        s_flag[0] = (old == SPLIT - 1) ? 1 : 0;
    }
    __syncthreads();
    if (s_flag[0]) {
        __threadfence();                 // acquire: other CTAs' partials visible
        if (tid == 0) g_cnt[b] = 0;      // reset for next graph replay
        float num0 = 0.f, num1 = 0.f, dsum = 0.f;
        #pragma unroll 4
        for (int i = 0; i < SPLIT; i++) {
            const size_t base = (size_t)(b * SPLIT + i) * ND;
            num0 += g_num[base + tid];
            num1 += g_num[base + tid + 128];
            dsum += g_den[b * SPLIT + i];
        }
        const float inv = __fdividef(1.0f, dsum);
        out[b * ND + tid]       = num0 * inv;
        out[b * ND + tid + 128] = num1 * inv;
    }
}

extern "C" void kernel_launch(void* const* d_in, const int* in_sizes, int n_in,
                              void* d_out, int out_size)
{
    const float* aspect = (const float*)d_in[0];  // (64, 1, 256)
    const float* memory = (const float*)d_in[1];  // (64, 4096, 256)
    const float* W      = (const float*)d_in[2];  // (512, 1)
    const float* bias   = (const float*)d_in[3];  // (1,)
    float* out = (float*)d_out;                   // (64, 256)

    static bool attr_set = false;
    if (!attr_set) {
        cudaFuncSetAttribute(att_fused,
                             cudaFuncAttributeMaxDynamicSharedMemorySize, SM_TOTAL);
        attr_set = true;
    }

    dim3 grid(SPLIT, NB);                 // 1024 CTAs, smem-limited 4/SM
    att_fused<<<grid, BLOCK, SM_TOTAL>>>(aspect, memory, W, bias, out);
}

// round 11
// speedup vs baseline: 1.9509x; 1.0336x over previous
#include <cuda_runtime.h>
#include <math.h>
#include <stdint.h>

#define NB 64
#define NS 4096
#define ND 256
#define SPLIT 16
#define CHUNK (NS / SPLIT)            // 256 rows per CTA
#define NCW 4                         // consumer warps
#define BLOCK (32 * (NCW + 1))        // 160: 4 consumer + 1 producer warp
#define TILE_ROWS 8
#define NTILES (CHUNK / TILE_ROWS)    // 32 tiles per CTA
#define TILE_BYTES (TILE_ROWS * ND * 4)   // 8192
#define DEPTH 3                       // ring depth
#define RPWT (TILE_ROWS / NCW)        // 2 rows per consumer warp per tile

// smem layout (dynamic)
#define SM_BUF    0
#define SM_FULL   (DEPTH * TILE_BYTES)            // 24576
#define SM_EMPTY  (SM_FULL + DEPTH * 8)
#define SM_ACC    (((SM_EMPTY + DEPTH * 8) + 15) & ~15)
#define SM_DEN    (SM_ACC + NCW * ND * 4)
#define SM_RED    (SM_DEN + NCW * 4)
#define SM_FLAG   (SM_RED + NCW * 4)
#define SM_TOTAL  (SM_FLAG + 16)

__device__ float g_num[NB * SPLIT * ND];
__device__ float g_den[NB * SPLIT];
__device__ unsigned int g_cnt[NB];    // zero-init; winning CTA resets

__device__ __forceinline__ float tanh_fast(float x) {
    float e = __expf(2.0f * x);
    return 1.0f - __fdividef(2.0f, e + 1.0f);
}

__device__ __forceinline__ void mbar_init(uint32_t mbar, uint32_t count) {
    asm volatile("mbarrier.init.shared.b64 [%0], %1;" :: "r"(mbar), "r"(count) : "memory");
}
__device__ __forceinline__ void mbar_expect_tx(uint32_t mbar, uint32_t bytes) {
    asm volatile("mbarrier.arrive.expect_tx.shared.b64 _, [%0], %1;"
                 :: "r"(mbar), "r"(bytes) : "memory");
}
__device__ __forceinline__ void mbar_arrive(uint32_t mbar) {
    asm volatile("mbarrier.arrive.release.cta.shared::cta.b64 _, [%0];"
                 :: "r"(mbar) : "memory");
}
__device__ __forceinline__ void bulk_cp(uint32_t dst, const void* src, uint32_t mbar) {
    asm volatile("cp.async.bulk.shared::cta.global.mbarrier::complete_tx::bytes "
                 "[%0], [%1], %2, [%3];"
                 :: "r"(dst), "l"(src), "r"((uint32_t)TILE_BYTES), "r"(mbar) : "memory");
}
__device__ __forceinline__ void mbar_wait(uint32_t mbar, uint32_t parity) {
    uint32_t done;
    asm volatile("{\n\t.reg .pred p;\n\t"
                 "mbarrier.try_wait.parity.acquire.cta.shared::cta.b64 p, [%1], %2;\n\t"
                 "selp.b32 %0, 1, 0, p;\n\t}"
                 : "=r"(done) : "r"(mbar), "r"(parity) : "memory");
    if (!done) {
        asm volatile("{\n\t.reg .pred P1;\n\t"
                     "W_%=:\n\t"
                     "mbarrier.try_wait.parity.acquire.cta.shared::cta.b64 P1, [%0], %1, 0x989680;\n\t"
                     "@P1 bra.uni D_%=;\n\t"
                     "bra.uni W_%=;\n\t"
                     "D_%=:\n\t}"
                     :: "r"(mbar), "r"(parity) : "memory");
    }
}

__global__ __launch_bounds__(BLOCK)
void att_fused(const float* __restrict__ aspect,
               const float* __restrict__ memory,
               const float* __restrict__ W,
               const float* __restrict__ bias,
               float* __restrict__ out)
{
    extern __shared__ char smem[];
    float* sbuf   = (float*)(smem + SM_BUF);
    float* s_acc  = (float*)(smem + SM_ACC);     // [NCW][ND]
    float* s_den  = (float*)(smem + SM_DEN);
    float* s_red  = (float*)(smem + SM_RED);
    int*   s_flag = (int*)  (smem + SM_FLAG);
    const uint32_t smem_u32 = (uint32_t)__cvta_generic_to_shared(smem);
    const uint32_t full0  = smem_u32 + SM_FULL;
    const uint32_t empty0 = smem_u32 + SM_EMPTY;

    const int b     = blockIdx.y;
    const int chunk = blockIdx.x;
    const int tid   = threadIdx.x;
    const int warp  = tid >> 5;
    const int lane  = tid & 31;

    const float* memb = memory + ((size_t)b * NS + (size_t)chunk * CHUNK) * ND;

    if (tid == 0) {
        #pragma unroll
        for (int s = 0; s < DEPTH; s++) {
            mbar_init(full0  + s * 8, 1);    // producer's expect_tx arrive
            mbar_init(empty0 + s * 8, NCW);  // one arrive per consumer warp
        }
        asm volatile("fence.proxy.async.shared::cta;" ::: "memory");
    }

    // a_b = aspect[b].Wa + bias — computed by ALL before the role split;
    // the __syncthreads below orders both s_red and the mbarrier inits.
    if (tid < 128) {
        float av = aspect[b * ND + tid]       * W[ND + tid]
                 + aspect[b * ND + tid + 128] * W[ND + tid + 128];
        #pragma unroll
        for (int o = 16; o; o >>= 1) av += __shfl_xor_sync(0xFFFFFFFFu, av, o);
        if (lane == 0) s_red[warp] = av;
    }
    __syncthreads();
    const float a_b = bias[0] + s_red[0] + s_red[1] + s_red[2] + s_red[3];

    // ───────── producer warp ─────────
    if (warp == NCW) {
        if (lane == 0) {
            int slot = 0; uint32_t phase = 1;   // first DEPTH empty-waits pass
            #pragma unroll 1
            for (int t = 0; t < NTILES; t++) {
                mbar_wait(empty0 + slot * 8, phase);
                mbar_expect_tx(full0 + slot * 8, TILE_BYTES);
                bulk_cp(smem_u32 + SM_BUF + slot * TILE_BYTES,
                        memb + (size_t)t * TILE_ROWS * ND, full0 + slot * 8);
                if (++slot == DEPTH) { slot = 0; phase ^= 1; }
            }
        }
    } else {
        // ───────── consumer warps ─────────
        float w[8];                                  // lane owns dims {lane+32k}
        #pragma unroll
        for (int k = 0; k < 8; k++) w[k] = W[lane + 32 * k];

        float acc[8] = {0.f,0.f,0.f,0.f,0.f,0.f,0.f,0.f};
        float den = 0.f;

        int slot = 0; uint32_t phase = 0;
        #pragma unroll 1
        for (int t = 0; t < NTILES; t++) {
            mbar_wait(full0 + slot * 8, phase);

            const float* srow = sbuf + slot * (TILE_ROWS * ND) + (warp * RPWT) * ND + lane;
            float m[RPWT][8];
            #pragma unroll
            for (int r = 0; r < RPWT; r++)
                #pragma unroll
                for (int k = 0; k < 8; k++)
                    m[r][k] = srow[r * ND + 32 * k];

            // dot: consumes every loaded value -> slot fully read after this
            float d[RPWT];
            #pragma unroll
            for (int r = 0; r < RPWT; r++) {
                float s = m[r][0] * w[0];
                #pragma unroll
                for (int k = 1; k < 8; k++) s = fmaf(m[r][k], w[k], s);
                d[r] = s;
            }

            // slot data now in registers: release for refill before the tail
            if (lane == 0) mbar_arrive(empty0 + slot * 8);

            #pragma unroll
            for (int o = 16; o; o >>= 1) {
                #pragma unroll
                for (int r = 0; r < RPWT; r++)
                    d[r] += __shfl_xor_sync(0xFFFFFFFFu, d[r], o);
            }
            #pragma unroll
            for (int r = 0; r < RPWT; r++) {
                const float gi = tanh_fast(d[r] + a_b);
                const float g  = __expf(gi - 1.0f);   // gi in [-1,1]: fixed max=1
                den += g;
                #pragma unroll
                for (int k = 0; k < 8; k++) acc[k] = fmaf(g, m[r][k], acc[k]);
            }

            if (++slot == DEPTH) { slot = 0; phase ^= 1; }
        }

        #pragma unroll
        for (int k = 0; k < 8; k++) s_acc[warp * ND + lane + 32 * k] = acc[k];
        if (lane == 0) s_den[warp] = den;
    }

    __syncthreads();

    // per-CTA partial -> gmem (consumer threads only: tid < 128)
    const int idx = b * SPLIT + chunk;
    if (tid < 128) {
        #pragma unroll
        for (int k = 0; k < 2; k++) {
            const int d = tid + k * 128;
            g_num[(size_t)idx * ND + d] =
                s_acc[0 * ND + d] + s_acc[1 * ND + d] + s_acc[2 * ND + d] + s_acc[3 * ND + d];
        }
    }
    if (tid == 0)
        g_den[idx] = s_den[0] + s_den[1] + s_den[2] + s_den[3];

    // fused finisher: last CTA of this batch reduces SPLIT partials
    __threadfence();
    __syncthreads();
    if (tid == 0) {
        unsigned old = atomicAdd(&g_cnt[b], 1u);
        s_flag[0] = (old == SPLIT - 1) ? 1 : 0;
    }
    __syncthreads();
    if (s_flag[0]) {
        __threadfence();                 // acquire: other CTAs' partials visible
        if (tid == 0) g_cnt[b] = 0;      // reset for next graph replay
        if (tid < 128) {
            float num0 = 0.f, num1 = 0.f, dsum = 0.f;
            #pragma unroll 4
            for (int i = 0; i < SPLIT; i++) {
                const size_t base = (size_t)(b * SPLIT + i) * ND;
                num0 += g_num[base + tid];
                num1 += g_num[base + tid + 128];
                dsum += g_den[b * SPLIT + i];
            }
            const float inv = __fdividef(1.0f, dsum);
            out[b * ND + tid]       = num0 * inv;
            out[b * ND + tid + 128] = num1 * inv;
        }
    }
}

extern "C" void kernel_launch(void* const* d_in, const int* in_sizes, int n_in,
                              void* d_out, int out_size)
{
    const float* aspect = (const float*)d_in[0];  // (64, 1, 256)
    const float* memory = (const float*)d_in[1];  // (64, 4096, 256)
    const float* W      = (const float*)d_in[2];  // (512, 1)
    const float* bias   = (const float*)d_in[3];  // (1,)
    float* out = (float*)d_out;                   // (64, 256)

    static bool attr_set = false;
    if (!attr_set) {
        cudaFuncSetAttribute(att_fused,
                             cudaFuncAttributeMaxDynamicSharedMemorySize, SM_TOTAL);
        attr_set = true;
    }

    dim3 grid(SPLIT, NB);                 // 1024 CTAs, 8/SM -> single wave
    att_fused<<<grid, BLOCK, SM_TOTAL>>>(aspect, memory, W, bias, out);
}